// round 8
// baseline (speedup 1.0000x reference)
#include <cuda_runtime.h>
#include <cuda_bf16.h>
#include <cstdint>
#include <cstddef>

#define BT 2048
#define HS 2048
#define HT 4096
#define VV 32000
#define IGNORE_IDX (-100)

#define BM 128
#define BN 256
#define BK 64                     // bf16 elems per K-tile = 128 bytes per row
#define STAGES 3
#define KT_S (HS / BK)            // 32 student K-tiles
#define KT_T (HT / BK)            // 64 teacher K-tiles
#define NKT (KT_S + KT_T)         // 96
#define A_BYTES (BM * 128)        // 16384
#define B_BYTES (BN * 128)        // 32768
#define STAGE_BYTES (A_BYTES + B_BYTES)          // 49152
#define SBUF_OFF (STAGES * STAGE_BYTES)          // 147456
#define SBUF_ROW 528                              // (256+8) bf16 -> conflict-free
#define SMEM_BYTES (SBUF_OFF + BM * SBUF_ROW)     // 215040

#define SWZ(x) ((x) ^ (((x) >> 3) & 0x70))

// ---------------- bf16 scratch -----------------------------------------------
__device__ __align__(16) __nv_bfloat16 g_sbf[(size_t)BT * HS];
__device__ __align__(16) __nv_bfloat16 g_tbf[(size_t)BT * HT];
__device__ __align__(16) __nv_bfloat16 g_swbf[(size_t)VV * HS];
__device__ __align__(16) __nv_bfloat16 g_twbf[(size_t)VV * HT];

__device__ float g_sumexp[BT];
__device__ float g_ss[BT];
__device__ float g_tt[BT];
__device__ float g_st[BT];
__device__ float g_tgt[BT];

// ---------------- asm helpers ------------------------------------------------
__device__ __forceinline__ uint32_t smem_u32(const void* p) {
    uint32_t a;
    asm("{ .reg .u64 t; cvta.to.shared.u64 t, %1; cvt.u32.u64 %0, t; }" : "=r"(a) : "l"(p));
    return a;
}
__device__ __forceinline__ void cp_async16(uint32_t dst, const void* src) {
    asm volatile("cp.async.cg.shared.global [%0], [%1], 16;" :: "r"(dst), "l"(src) : "memory");
}
__device__ __forceinline__ void cp_commit() {
    asm volatile("cp.async.commit_group;" ::: "memory");
}
__device__ __forceinline__ void ldsm_x4(uint32_t* r, uint32_t addr) {
    asm volatile("ldmatrix.sync.aligned.m8n8.x4.shared.b16 {%0,%1,%2,%3}, [%4];"
                 : "=r"(r[0]), "=r"(r[1]), "=r"(r[2]), "=r"(r[3]) : "r"(addr));
}
__device__ __forceinline__ void mma16816(float* d, const uint32_t* a, uint32_t b0, uint32_t b1) {
    asm volatile(
        "mma.sync.aligned.m16n8k16.row.col.f32.bf16.bf16.f32 "
        "{%0,%1,%2,%3}, {%4,%5,%6,%7}, {%8,%9}, {%0,%1,%2,%3};"
        : "+f"(d[0]), "+f"(d[1]), "+f"(d[2]), "+f"(d[3])
        : "r"(a[0]), "r"(a[1]), "r"(a[2]), "r"(a[3]), "r"(b0), "r"(b1));
}

// ---------------- Kernel: fp32 -> bf16 (which==0 also zeroes accumulators) ---
__global__ void cvt_kernel(const float4* __restrict__ in, int which, size_t n4) {
    if (which == 0) {
        int gid = blockIdx.x * blockDim.x + threadIdx.x;
        if (gid < BT) {
            g_sumexp[gid] = 0.f; g_ss[gid] = 0.f; g_tt[gid] = 0.f; g_st[gid] = 0.f;
        }
    }
    __nv_bfloat162* out;
    switch (which) {
        case 0: out = (__nv_bfloat162*)g_sbf; break;
        case 1: out = (__nv_bfloat162*)g_tbf; break;
        case 2: out = (__nv_bfloat162*)g_swbf; break;
        default: out = (__nv_bfloat162*)g_twbf; break;
    }
    size_t stride = (size_t)gridDim.x * blockDim.x;
    for (size_t i = (size_t)blockIdx.x * blockDim.x + threadIdx.x; i < n4; i += stride) {
        float4 v = in[i];
        out[2 * i + 0] = __floats2bfloat162_rn(v.x, v.y);
        out[2 * i + 1] = __floats2bfloat162_rn(v.z, v.w);
    }
}

// ---------------- Kernel: exact fp32 target logit -----------------------------
__global__ void tgt_kernel(const float* __restrict__ student,
                           const float* __restrict__ sw,
                           const int* __restrict__ target) {
    int row = blockIdx.x;
    int t = target[row];
    int ct = (t < 0 || t >= VV) ? 0 : t;
    const float4* a = (const float4*)(student + (size_t)row * HS);
    const float4* b = (const float4*)(sw + (size_t)ct * HS);
    float p = 0.f;
    for (int k = threadIdx.x; k < HS / 4; k += blockDim.x) {
        float4 x = a[k]; float4 y = b[k];
        p += x.x * y.x + x.y * y.y + x.z * y.z + x.w * y.w;
    }
    __shared__ float sred[8];
    #pragma unroll
    for (int o = 16; o; o >>= 1) p += __shfl_down_sync(0xffffffffu, p, o);
    if ((threadIdx.x & 31) == 0) sred[threadIdx.x >> 5] = p;
    __syncthreads();
    if (threadIdx.x < 32) {
        p = (threadIdx.x < (blockDim.x >> 5)) ? sred[threadIdx.x] : 0.f;
        #pragma unroll
        for (int o = 16; o; o >>= 1) p += __shfl_down_sync(0xffffffffu, p, o);
        if (threadIdx.x == 0) g_tgt[row] = p;
    }
}

// ---------------- Kernel: two-phase dual bf16 HMMA GEMM + row stats ----------
// Grid (16, 125). Block tile 128x256; 8 warps as 2m x 4n, warp tile 64x64.
// Fragments double-buffered in registers. kf offset composed with XOR:
// SWZ(x + kf*32) == SWZ(x) ^ (kf*32) when bits5-6 of x are 0 (kf*32 never
// touches the XOR source bits 7-9). ADD would carry out of bits 5-6 (R7 bug).
__global__ __launch_bounds__(256, 1) void main_kernel() {
    extern __shared__ char smem[];
    const uint32_t sb = smem_u32(smem);
    const int tid = threadIdx.x;
    const int wid = tid >> 5;
    const int lane = tid & 31;
    const int mw = wid & 1;        // 2 warps in m
    const int nw = wid >> 1;       // 4 warps in n
    const int rb = blockIdx.x * BM;
    const int vb = blockIdx.y * BN;

    const int q = tid & 7;     // 16B chunk within 128B row
    const int r0 = tid >> 3;   // base row 0..31

    float acc[4][8][4];        // 64x64 warp tile
    #pragma unroll
    for (int i = 0; i < 4; i++)
        #pragma unroll
        for (int j = 0; j < 8; j++)
            #pragma unroll
            for (int e = 0; e < 4; e++) acc[i][j][e] = 0.f;

    auto issue = [&](int kt, int s) {
        const bool tea = (kt >= KT_S);
        const int kk = tea ? (kt - KT_S) : kt;
        const __nv_bfloat16* Ab = tea ? g_tbf : g_sbf;
        const __nv_bfloat16* Bb = tea ? g_twbf : g_swbf;
        const int ldk = tea ? HT : HS;
        const uint32_t st = sb + s * STAGE_BYTES;
        #pragma unroll
        for (int c = 0; c < 4; c++) {
            int row = r0 + 32 * c;
            cp_async16(st + SWZ(row * 128 + q * 16),
                       Ab + (size_t)(rb + row) * ldk + kk * BK + q * 8);
        }
        #pragma unroll
        for (int c = 0; c < 8; c++) {
            int row = r0 + 32 * c;
            cp_async16(st + A_BYTES + SWZ(row * 128 + q * 16),
                       Bb + (size_t)(vb + row) * ldk + kk * BK + q * 8);
        }
        cp_commit();
    };

    const int arow = mw * 64 + (lane & 15);   // + mi*16
    const int brow = nw * 64 + (lane & 15);   // + np*16
    const int csel = (lane >> 4) * 16;

    // kf-invariant swizzled offsets (bits 5-6 of the pre-swizzle address are 0,
    // so per-kf offset composes via XOR with kf*32)
    uint32_t aoff[4], boff[4];
    #pragma unroll
    for (int mi = 0; mi < 4; mi++) aoff[mi] = SWZ((arow + mi * 16) * 128 + csel);
    #pragma unroll
    for (int np = 0; np < 4; np++) boff[np] = A_BYTES + SWZ((brow + np * 16) * 128 + csel);

    auto step = [&](int kt) __attribute__((always_inline)) {
        const int s = kt % STAGES;
        if (kt < NKT - 1) {
            asm volatile("cp.async.wait_group 1;" ::: "memory");
        } else {
            asm volatile("cp.async.wait_group 0;" ::: "memory");
        }
        __syncthreads();
        if (kt + 2 < NKT) issue(kt + 2, (kt + 2) % STAGES);

        const uint32_t st = sb + s * STAGE_BYTES;

        uint32_t af[2][4][4], bfv[2][4][4];
        #pragma unroll
        for (int mi = 0; mi < 4; mi++) ldsm_x4(af[0][mi], st + aoff[mi]);
        #pragma unroll
        for (int np = 0; np < 4; np++) ldsm_x4(bfv[0][np], st + boff[np]);

        #pragma unroll
        for (int kf = 0; kf < 4; kf++) {
            const int cur = kf & 1, nxt = cur ^ 1;
            if (kf < 3) {
                const uint32_t ko = (uint32_t)(kf + 1) * 32;
                #pragma unroll
                for (int mi = 0; mi < 4; mi++)
                    ldsm_x4(af[nxt][mi], st + (aoff[mi] ^ ko));
                #pragma unroll
                for (int np = 0; np < 4; np++)
                    ldsm_x4(bfv[nxt][np], st + (boff[np] ^ ko));
            }
            #pragma unroll
            for (int mi = 0; mi < 4; mi++)
                #pragma unroll
                for (int np = 0; np < 4; np++) {
                    mma16816(acc[mi][2 * np + 0], af[cur][mi], bfv[cur][np][0], bfv[cur][np][2]);
                    mma16816(acc[mi][2 * np + 1], af[cur][mi], bfv[cur][np][1], bfv[cur][np][3]);
                }
        }
    };

    issue(0, 0);
    issue(1, 1);

    // ---- phase 1: student ----
    for (int kt = 0; kt < KT_S; kt++) step(kt);

    // phase boundary: exp/ss stats from full-precision s; stash s (bf16) in smem.
    {
        const uint32_t lane_col_b = (uint32_t)(nw * 64 + (lane & 3) * 2) * 2;
        #pragma unroll
        for (int mi = 0; mi < 4; mi++) {
            #pragma unroll
            for (int half = 0; half < 2; half++) {
                int row = mw * 64 + mi * 16 + (lane >> 2) + half * 8;
                uint32_t rowoff = sb + SBUF_OFF + (uint32_t)row * SBUF_ROW + lane_col_b;
                float pe = 0.f, pss = 0.f;
                #pragma unroll
                for (int ni = 0; ni < 8; ni++) {
                    float s0 = acc[mi][ni][half * 2 + 0];
                    float s1 = acc[mi][ni][half * 2 + 1];
                    pe += __expf(s0) + __expf(s1);
                    pss += s0 * s0 + s1 * s1;
                    __nv_bfloat162 p = __floats2bfloat162_rn(s0, s1);
                    uint32_t pw = *(uint32_t*)&p;
                    asm volatile("st.shared.b32 [%0], %1;" :: "r"(rowoff + ni * 16), "r"(pw) : "memory");
                }
                #pragma unroll
                for (int o = 1; o < 4; o <<= 1) {
                    pe += __shfl_xor_sync(0xffffffffu, pe, o);
                    pss += __shfl_xor_sync(0xffffffffu, pss, o);
                }
                if ((lane & 3) == 0) {
                    atomicAdd(&g_sumexp[rb + row], pe);
                    atomicAdd(&g_ss[rb + row], pss);
                }
            }
        }
        #pragma unroll
        for (int i = 0; i < 4; i++)
            #pragma unroll
            for (int j = 0; j < 8; j++)
                #pragma unroll
                for (int e = 0; e < 4; e++) acc[i][j][e] = 0.f;
    }

    // ---- phase 2: teacher ----
    for (int kt = KT_S; kt < NKT; kt++) step(kt);

    // final epilogue: tt/st stats (s read back from smem, lane-private values).
    {
        const uint32_t lane_col_b = (uint32_t)(nw * 64 + (lane & 3) * 2) * 2;
        #pragma unroll
        for (int mi = 0; mi < 4; mi++) {
            #pragma unroll
            for (int half = 0; half < 2; half++) {
                int row = mw * 64 + mi * 16 + (lane >> 2) + half * 8;
                uint32_t rowoff = sb + SBUF_OFF + (uint32_t)row * SBUF_ROW + lane_col_b;
                float ptt = 0.f, pst = 0.f;
                #pragma unroll
                for (int ni = 0; ni < 8; ni++) {
                    uint32_t pw;
                    asm volatile("ld.shared.b32 %0, [%1];" : "=r"(pw) : "r"(rowoff + ni * 16));
                    __nv_bfloat162 p = *(__nv_bfloat162*)&pw;
                    float s0 = __bfloat162float(p.x);
                    float s1 = __bfloat162float(p.y);
                    float t0 = acc[mi][ni][half * 2 + 0];
                    float t1 = acc[mi][ni][half * 2 + 1];
                    ptt += t0 * t0 + t1 * t1;
                    pst += s0 * t0 + s1 * t1;
                }
                #pragma unroll
                for (int o = 1; o < 4; o <<= 1) {
                    ptt += __shfl_xor_sync(0xffffffffu, ptt, o);
                    pst += __shfl_xor_sync(0xffffffffu, pst, o);
                }
                if ((lane & 3) == 0) {
                    atomicAdd(&g_tt[rb + row], ptt);
                    atomicAdd(&g_st[rb + row], pst);
                }
            }
        }
    }
}

// ---------------- Kernel: final scalar loss ----------------------------------
__global__ void final_kernel(const int* __restrict__ target, float* __restrict__ out) {
    __shared__ float sh[8], ssf[8], snv[8];
    float hard = 0.f, soft = 0.f, nv = 0.f;
    for (int i = threadIdx.x; i < BT; i += blockDim.x) {
        int t = target[i];
        bool valid = (t != IGNORE_IDX);
        float lse = logf(g_sumexp[i]);
        if (valid) { hard += lse - g_tgt[i]; nv += 1.f; }
        float cs = g_st[i] * rsqrtf(g_ss[i] + 1e-12f) * rsqrtf(g_tt[i] + 1e-12f);
        soft += 1.f - cs;
    }
    #pragma unroll
    for (int o = 16; o; o >>= 1) {
        hard += __shfl_down_sync(0xffffffffu, hard, o);
        soft += __shfl_down_sync(0xffffffffu, soft, o);
        nv += __shfl_down_sync(0xffffffffu, nv, o);
    }
    int w = threadIdx.x >> 5, l = threadIdx.x & 31;
    if (l == 0) { sh[w] = hard; ssf[w] = soft; snv[w] = nv; }
    __syncthreads();
    if (threadIdx.x < 32) {
        int nw = blockDim.x >> 5;
        hard = (threadIdx.x < nw) ? sh[threadIdx.x] : 0.f;
        soft = (threadIdx.x < nw) ? ssf[threadIdx.x] : 0.f;
        nv = (threadIdx.x < nw) ? snv[threadIdx.x] : 0.f;
        #pragma unroll
        for (int o = 16; o; o >>= 1) {
            hard += __shfl_down_sync(0xffffffffu, hard, o);
            soft += __shfl_down_sync(0xffffffffu, soft, o);
            nv += __shfl_down_sync(0xffffffffu, nv, o);
        }
        if (threadIdx.x == 0)
            out[0] = 0.5f * hard / nv + 0.5f * soft / nv;
    }
}

// ---------------- launch ------------------------------------------------------
extern "C" void kernel_launch(void* const* d_in, const int* in_sizes, int n_in,
                              void* d_out, int out_size) {
    const float* student = (const float*)d_in[0];
    const float* teacher = (const float*)d_in[1];
    const int* target = (const int*)d_in[2];
    const float* sw = (const float*)d_in[3];
    const float* tw = (const float*)d_in[4];
    float* out = (float*)d_out;

    cudaFuncSetAttribute(main_kernel, cudaFuncAttributeMaxDynamicSharedMemorySize, SMEM_BYTES);

    cvt_kernel<<<2048, 256>>>((const float4*)student, 0, (size_t)BT * HS / 4);  // idx 0 (+zero)
    cvt_kernel<<<2048, 256>>>((const float4*)teacher, 1, (size_t)BT * HT / 4);  // idx 1
    cvt_kernel<<<4096, 256>>>((const float4*)sw, 2, (size_t)VV * HS / 4);       // idx 2
    cvt_kernel<<<4096, 256>>>((const float4*)tw, 3, (size_t)VV * HT / 4);       // idx 3
    tgt_kernel<<<BT, 128>>>(student, sw, target);                               // idx 4
    dim3 grid(BT / BM, VV / BN);  // (16, 125)
    main_kernel<<<grid, 256, SMEM_BYTES>>>();                                   // idx 5
    final_kernel<<<1, 256>>>(target, out);                                      // idx 6
}

// round 9
// speedup vs baseline: 1.0117x; 1.0117x over previous
#include <cuda_runtime.h>
#include <cuda_bf16.h>
#include <cstdint>
#include <cstddef>

#define BT 2048
#define HS 2048
#define HT 4096
#define VV 32000
#define IGNORE_IDX (-100)

#define BM 128
#define BN 256
#define BK 128                    // fp8 elems per K-tile = 128 bytes per row
#define STAGES 3
#define KT_S (HS / BK)            // 16 student K-tiles
#define KT_T (HT / BK)            // 32 teacher K-tiles
#define NKT (KT_S + KT_T)         // 48
#define A_BYTES (BM * 128)        // 16384
#define B_BYTES (BN * 128)        // 32768
#define STAGE_BYTES (A_BYTES + B_BYTES)          // 49152
#define SBUF_OFF (STAGES * STAGE_BYTES)          // 147456
#define SBUF_ROW 528                              // (256+8) bf16 -> conflict-free
#define SMEM_BYTES (SBUF_OFF + BM * SBUF_ROW)     // 215040

#define WSCALE 64.0f              // weight scale before fp8 quantization (2^6)
#define ISCALE (1.0f / 64.0f)     // logit un-scale in epilogue

#define SWZ(x) ((x) ^ (((x) >> 3) & 0x70))

// ---------------- fp8 scratch --------------------------------------------------
__device__ __align__(16) uint8_t g_s8[(size_t)BT * HS];
__device__ __align__(16) uint8_t g_t8[(size_t)BT * HT];
__device__ __align__(16) uint8_t g_sw8[(size_t)VV * HS];
__device__ __align__(16) uint8_t g_tw8[(size_t)VV * HT];

__device__ float g_sumexp[BT];
__device__ float g_ss[BT];
__device__ float g_tt[BT];
__device__ float g_st[BT];
__device__ float g_tgt[BT];

// ---------------- asm helpers ------------------------------------------------
__device__ __forceinline__ uint32_t smem_u32(const void* p) {
    uint32_t a;
    asm("{ .reg .u64 t; cvta.to.shared.u64 t, %1; cvt.u32.u64 %0, t; }" : "=r"(a) : "l"(p));
    return a;
}
__device__ __forceinline__ void cp_async16(uint32_t dst, const void* src) {
    asm volatile("cp.async.cg.shared.global [%0], [%1], 16;" :: "r"(dst), "l"(src) : "memory");
}
__device__ __forceinline__ void cp_commit() {
    asm volatile("cp.async.commit_group;" ::: "memory");
}
__device__ __forceinline__ void ldsm_x4(uint32_t* r, uint32_t addr) {
    asm volatile("ldmatrix.sync.aligned.m8n8.x4.shared.b16 {%0,%1,%2,%3}, [%4];"
                 : "=r"(r[0]), "=r"(r[1]), "=r"(r[2]), "=r"(r[3]) : "r"(addr));
}
// fp8 e4m3 MMA, K=32: same operand register shape as bf16 m16n8k16.
__device__ __forceinline__ void mma16832(float* d, const uint32_t* a, uint32_t b0, uint32_t b1) {
    asm volatile(
        "mma.sync.aligned.m16n8k32.row.col.f32.e4m3.e4m3.f32 "
        "{%0,%1,%2,%3}, {%4,%5,%6,%7}, {%8,%9}, {%0,%1,%2,%3};"
        : "+f"(d[0]), "+f"(d[1]), "+f"(d[2]), "+f"(d[3])
        : "r"(a[0]), "r"(a[1]), "r"(a[2]), "r"(a[3]), "r"(b0), "r"(b1));
}
// pack 4 floats into 4 consecutive e4m3 bytes (element k at byte k)
__device__ __forceinline__ uint32_t pack_e4m3_4(float a, float b, float c, float d) {
    uint16_t lo, hi;
    asm("cvt.rn.satfinite.e4m3x2.f32 %0, %1, %2;" : "=h"(lo) : "f"(b), "f"(a));
    asm("cvt.rn.satfinite.e4m3x2.f32 %0, %1, %2;" : "=h"(hi) : "f"(d), "f"(c));
    return (uint32_t)lo | ((uint32_t)hi << 16);
}

// ---------------- Kernel: fp32 -> fp8 (scaled); which==0 also zeroes accums --
__global__ void cvt_kernel(const float4* __restrict__ in, int which, size_t n4, float scale) {
    if (which == 0) {
        int gid = blockIdx.x * blockDim.x + threadIdx.x;
        if (gid < BT) {
            g_sumexp[gid] = 0.f; g_ss[gid] = 0.f; g_tt[gid] = 0.f; g_st[gid] = 0.f;
        }
    }
    uint32_t* out;
    switch (which) {
        case 0: out = (uint32_t*)g_s8; break;
        case 1: out = (uint32_t*)g_t8; break;
        case 2: out = (uint32_t*)g_sw8; break;
        default: out = (uint32_t*)g_tw8; break;
    }
    size_t stride = (size_t)gridDim.x * blockDim.x;
    for (size_t i = (size_t)blockIdx.x * blockDim.x + threadIdx.x; i < n4; i += stride) {
        float4 v = in[i];
        out[i] = pack_e4m3_4(v.x * scale, v.y * scale, v.z * scale, v.w * scale);
    }
}

// ---------------- Kernel: exact fp32 target logit -----------------------------
__global__ void tgt_kernel(const float* __restrict__ student,
                           const float* __restrict__ sw,
                           const int* __restrict__ target) {
    int row = blockIdx.x;
    int t = target[row];
    int ct = (t < 0 || t >= VV) ? 0 : t;
    const float4* a = (const float4*)(student + (size_t)row * HS);
    const float4* b = (const float4*)(sw + (size_t)ct * HS);
    float p = 0.f;
    for (int k = threadIdx.x; k < HS / 4; k += blockDim.x) {
        float4 x = a[k]; float4 y = b[k];
        p += x.x * y.x + x.y * y.y + x.z * y.z + x.w * y.w;
    }
    __shared__ float sred[8];
    #pragma unroll
    for (int o = 16; o; o >>= 1) p += __shfl_down_sync(0xffffffffu, p, o);
    if ((threadIdx.x & 31) == 0) sred[threadIdx.x >> 5] = p;
    __syncthreads();
    if (threadIdx.x < 32) {
        p = (threadIdx.x < (blockDim.x >> 5)) ? sred[threadIdx.x] : 0.f;
        #pragma unroll
        for (int o = 16; o; o >>= 1) p += __shfl_down_sync(0xffffffffu, p, o);
        if (threadIdx.x == 0) g_tgt[row] = p;
    }
}

// ---------------- Kernel: two-phase dual FP8 MMA GEMM + row stats ------------
// Grid (16, 125). Block tile 128x256; 8 warps as 2m x 4n, warp tile 64x64.
// K=32 per MMA (e4m3): half the MMA issues of the bf16 version.
__global__ __launch_bounds__(256, 1) void main_kernel() {
    extern __shared__ char smem[];
    const uint32_t sb = smem_u32(smem);
    const int tid = threadIdx.x;
    const int wid = tid >> 5;
    const int lane = tid & 31;
    const int mw = wid & 1;        // 2 warps in m
    const int nw = wid >> 1;       // 4 warps in n
    const int rb = blockIdx.x * BM;
    const int vb = blockIdx.y * BN;

    const int q = tid & 7;     // 16B chunk within 128B row
    const int r0 = tid >> 3;   // base row 0..31

    float acc[4][8][4];        // 64x64 warp tile
    #pragma unroll
    for (int i = 0; i < 4; i++)
        #pragma unroll
        for (int j = 0; j < 8; j++)
            #pragma unroll
            for (int e = 0; e < 4; e++) acc[i][j][e] = 0.f;

    auto issue = [&](int kt, int s) {
        const bool tea = (kt >= KT_S);
        const int kk = tea ? (kt - KT_S) : kt;
        const uint8_t* Ab = tea ? g_t8 : g_s8;
        const uint8_t* Bb = tea ? g_tw8 : g_sw8;
        const int ldk = tea ? HT : HS;    // bytes per row (1B/elem)
        const uint32_t st = sb + s * STAGE_BYTES;
        #pragma unroll
        for (int c = 0; c < 4; c++) {
            int row = r0 + 32 * c;
            cp_async16(st + SWZ(row * 128 + q * 16),
                       Ab + (size_t)(rb + row) * ldk + kk * BK + q * 16);
        }
        #pragma unroll
        for (int c = 0; c < 8; c++) {
            int row = r0 + 32 * c;
            cp_async16(st + A_BYTES + SWZ(row * 128 + q * 16),
                       Bb + (size_t)(vb + row) * ldk + kk * BK + q * 16);
        }
        cp_commit();
    };

    const int arow = mw * 64 + (lane & 15);   // + mi*16
    const int brow = nw * 64 + (lane & 15);   // + np*16
    const int csel = (lane >> 4) * 16;

    auto step = [&](int kt) __attribute__((always_inline)) {
        const int s = kt % STAGES;
        if (kt < NKT - 1) {
            asm volatile("cp.async.wait_group 1;" ::: "memory");
        } else {
            asm volatile("cp.async.wait_group 0;" ::: "memory");
        }
        __syncthreads();
        if (kt + 2 < NKT) issue(kt + 2, (kt + 2) % STAGES);

        const uint32_t stA = sb + s * STAGE_BYTES;
        const uint32_t stB = stA + A_BYTES;
        #pragma unroll
        for (int kf = 0; kf < 4; kf++) {   // kf covers 32 fp8 = 32 bytes
            uint32_t af[4][4], bfv[4][4];
            #pragma unroll
            for (int mi = 0; mi < 4; mi++)
                ldsm_x4(af[mi], stA + SWZ((arow + mi * 16) * 128 + kf * 32 + csel));
            #pragma unroll
            for (int np = 0; np < 4; np++)
                ldsm_x4(bfv[np], stB + SWZ((brow + np * 16) * 128 + kf * 32 + csel));
            #pragma unroll
            for (int mi = 0; mi < 4; mi++)
                #pragma unroll
                for (int np = 0; np < 4; np++) {
                    mma16832(acc[mi][2 * np + 0], af[mi], bfv[np][0], bfv[np][2]);
                    mma16832(acc[mi][2 * np + 1], af[mi], bfv[np][1], bfv[np][3]);
                }
        }
    };

    issue(0, 0);
    issue(1, 1);

    // ---- phase 1: student ----
    for (int kt = 0; kt < KT_S; kt++) step(kt);

    // phase boundary: unscale logits, exp/ss stats, stash s (bf16) in smem.
    {
        const uint32_t lane_col_b = (uint32_t)(nw * 64 + (lane & 3) * 2) * 2;
        #pragma unroll
        for (int mi = 0; mi < 4; mi++) {
            #pragma unroll
            for (int half = 0; half < 2; half++) {
                int row = mw * 64 + mi * 16 + (lane >> 2) + half * 8;
                uint32_t rowoff = sb + SBUF_OFF + (uint32_t)row * SBUF_ROW + lane_col_b;
                float pe = 0.f, pss = 0.f;
                #pragma unroll
                for (int ni = 0; ni < 8; ni++) {
                    float s0 = acc[mi][ni][half * 2 + 0] * ISCALE;
                    float s1 = acc[mi][ni][half * 2 + 1] * ISCALE;
                    pe += __expf(s0) + __expf(s1);
                    pss += s0 * s0 + s1 * s1;
                    __nv_bfloat162 p = __floats2bfloat162_rn(s0, s1);
                    uint32_t pw = *(uint32_t*)&p;
                    asm volatile("st.shared.b32 [%0], %1;" :: "r"(rowoff + ni * 16), "r"(pw) : "memory");
                }
                #pragma unroll
                for (int o = 1; o < 4; o <<= 1) {
                    pe += __shfl_xor_sync(0xffffffffu, pe, o);
                    pss += __shfl_xor_sync(0xffffffffu, pss, o);
                }
                if ((lane & 3) == 0) {
                    atomicAdd(&g_sumexp[rb + row], pe);
                    atomicAdd(&g_ss[rb + row], pss);
                }
            }
        }
        #pragma unroll
        for (int i = 0; i < 4; i++)
            #pragma unroll
            for (int j = 0; j < 8; j++)
                #pragma unroll
                for (int e = 0; e < 4; e++) acc[i][j][e] = 0.f;
    }

    // ---- phase 2: teacher ----
    for (int kt = KT_S; kt < NKT; kt++) step(kt);

    // final epilogue: tt/st stats (s read back from smem, lane-private values).
    {
        const uint32_t lane_col_b = (uint32_t)(nw * 64 + (lane & 3) * 2) * 2;
        #pragma unroll
        for (int mi = 0; mi < 4; mi++) {
            #pragma unroll
            for (int half = 0; half < 2; half++) {
                int row = mw * 64 + mi * 16 + (lane >> 2) + half * 8;
                uint32_t rowoff = sb + SBUF_OFF + (uint32_t)row * SBUF_ROW + lane_col_b;
                float ptt = 0.f, pst = 0.f;
                #pragma unroll
                for (int ni = 0; ni < 8; ni++) {
                    uint32_t pw;
                    asm volatile("ld.shared.b32 %0, [%1];" : "=r"(pw) : "r"(rowoff + ni * 16));
                    __nv_bfloat162 p = *(__nv_bfloat162*)&pw;
                    float s0 = __bfloat162float(p.x);
                    float s1 = __bfloat162float(p.y);
                    float t0 = acc[mi][ni][half * 2 + 0] * ISCALE;
                    float t1 = acc[mi][ni][half * 2 + 1] * ISCALE;
                    ptt += t0 * t0 + t1 * t1;
                    pst += s0 * t0 + s1 * t1;
                }
                #pragma unroll
                for (int o = 1; o < 4; o <<= 1) {
                    ptt += __shfl_xor_sync(0xffffffffu, ptt, o);
                    pst += __shfl_xor_sync(0xffffffffu, pst, o);
                }
                if ((lane & 3) == 0) {
                    atomicAdd(&g_tt[rb + row], ptt);
                    atomicAdd(&g_st[rb + row], pst);
                }
            }
        }
    }
}

// ---------------- Kernel: final scalar loss ----------------------------------
__global__ void final_kernel(const int* __restrict__ target, float* __restrict__ out) {
    __shared__ float sh[8], ssf[8], snv[8];
    float hard = 0.f, soft = 0.f, nv = 0.f;
    for (int i = threadIdx.x; i < BT; i += blockDim.x) {
        int t = target[i];
        bool valid = (t != IGNORE_IDX);
        float lse = logf(g_sumexp[i]);
        if (valid) { hard += lse - g_tgt[i]; nv += 1.f; }
        float cs = g_st[i] * rsqrtf(g_ss[i] + 1e-12f) * rsqrtf(g_tt[i] + 1e-12f);
        soft += 1.f - cs;
    }
    #pragma unroll
    for (int o = 16; o; o >>= 1) {
        hard += __shfl_down_sync(0xffffffffu, hard, o);
        soft += __shfl_down_sync(0xffffffffu, soft, o);
        nv += __shfl_down_sync(0xffffffffu, nv, o);
    }
    int w = threadIdx.x >> 5, l = threadIdx.x & 31;
    if (l == 0) { sh[w] = hard; ssf[w] = soft; snv[w] = nv; }
    __syncthreads();
    if (threadIdx.x < 32) {
        int nw = blockDim.x >> 5;
        hard = (threadIdx.x < nw) ? sh[threadIdx.x] : 0.f;
        soft = (threadIdx.x < nw) ? ssf[threadIdx.x] : 0.f;
        nv = (threadIdx.x < nw) ? snv[threadIdx.x] : 0.f;
        #pragma unroll
        for (int o = 16; o; o >>= 1) {
            hard += __shfl_down_sync(0xffffffffu, hard, o);
            soft += __shfl_down_sync(0xffffffffu, soft, o);
            nv += __shfl_down_sync(0xffffffffu, nv, o);
        }
        if (threadIdx.x == 0)
            out[0] = 0.5f * hard / nv + 0.5f * soft / nv;
    }
}

// ---------------- launch ------------------------------------------------------
extern "C" void kernel_launch(void* const* d_in, const int* in_sizes, int n_in,
                              void* d_out, int out_size) {
    const float* student = (const float*)d_in[0];
    const float* teacher = (const float*)d_in[1];
    const int* target = (const int*)d_in[2];
    const float* sw = (const float*)d_in[3];
    const float* tw = (const float*)d_in[4];
    float* out = (float*)d_out;

    cudaFuncSetAttribute(main_kernel, cudaFuncAttributeMaxDynamicSharedMemorySize, SMEM_BYTES);

    cvt_kernel<<<2048, 256>>>((const float4*)student, 0, (size_t)BT * HS / 4, 1.0f);
    cvt_kernel<<<2048, 256>>>((const float4*)teacher, 1, (size_t)BT * HT / 4, 1.0f);
    cvt_kernel<<<4096, 256>>>((const float4*)sw, 2, (size_t)VV * HS / 4, WSCALE);
    cvt_kernel<<<4096, 256>>>((const float4*)tw, 3, (size_t)VV * HT / 4, WSCALE);
    tgt_kernel<<<BT, 128>>>(student, sw, target);
    dim3 grid(BT / BM, VV / BN);  // (16, 125)
    main_kernel<<<grid, 256, SMEM_BYTES>>>();
    final_kernel<<<1, 256>>>(target, out);
}

// round 10
// speedup vs baseline: 1.0362x; 1.0242x over previous
#include <cuda_runtime.h>
#include <cuda_bf16.h>
#include <cstdint>
#include <cstddef>

#define BT 2048
#define HS 2048
#define HT 4096
#define VV 32000
#define IGNORE_IDX (-100)

#define BM 128
#define BN 256
#define BK 128                    // fp8 elems per K-tile = 128 bytes per row
#define THREADS 512
#define STAGES 3
#define KT_S (HS / BK)            // 16 student K-tiles
#define KT_T (HT / BK)            // 32 teacher K-tiles
#define NKT (KT_S + KT_T)         // 48
#define A_BYTES (BM * 128)        // 16384
#define B_BYTES (BN * 128)        // 32768
#define STAGE_BYTES (A_BYTES + B_BYTES)          // 49152
#define SBUF_OFF (STAGES * STAGE_BYTES)          // 147456
#define SBUF_ROW 528                              // (256+8) bf16 -> conflict-free
#define SMEM_BYTES (SBUF_OFF + BM * SBUF_ROW)     // 215040

#define WSCALE 64.0f              // weight scale before fp8 quantization (2^6)
#define ISCALE (1.0f / 64.0f)     // logit un-scale in epilogue

#define SWZ(x) ((x) ^ (((x) >> 3) & 0x70))

// ---------------- fp8 scratch --------------------------------------------------
__device__ __align__(16) uint8_t g_s8[(size_t)BT * HS];
__device__ __align__(16) uint8_t g_t8[(size_t)BT * HT];
__device__ __align__(16) uint8_t g_sw8[(size_t)VV * HS];
__device__ __align__(16) uint8_t g_tw8[(size_t)VV * HT];

__device__ float g_sumexp[BT];
__device__ float g_ss[BT];
__device__ float g_tt[BT];
__device__ float g_st[BT];
__device__ float g_tgt[BT];

// ---------------- asm helpers ------------------------------------------------
__device__ __forceinline__ uint32_t smem_u32(const void* p) {
    uint32_t a;
    asm("{ .reg .u64 t; cvta.to.shared.u64 t, %1; cvt.u32.u64 %0, t; }" : "=r"(a) : "l"(p));
    return a;
}
__device__ __forceinline__ void cp_async16(uint32_t dst, const void* src) {
    asm volatile("cp.async.cg.shared.global [%0], [%1], 16;" :: "r"(dst), "l"(src) : "memory");
}
__device__ __forceinline__ void cp_commit() {
    asm volatile("cp.async.commit_group;" ::: "memory");
}
__device__ __forceinline__ void ldsm_x4(uint32_t* r, uint32_t addr) {
    asm volatile("ldmatrix.sync.aligned.m8n8.x4.shared.b16 {%0,%1,%2,%3}, [%4];"
                 : "=r"(r[0]), "=r"(r[1]), "=r"(r[2]), "=r"(r[3]) : "r"(addr));
}
// fp8 e4m3 MMA, K=32
__device__ __forceinline__ void mma16832(float* d, const uint32_t* a, uint32_t b0, uint32_t b1) {
    asm volatile(
        "mma.sync.aligned.m16n8k32.row.col.f32.e4m3.e4m3.f32 "
        "{%0,%1,%2,%3}, {%4,%5,%6,%7}, {%8,%9}, {%0,%1,%2,%3};"
        : "+f"(d[0]), "+f"(d[1]), "+f"(d[2]), "+f"(d[3])
        : "r"(a[0]), "r"(a[1]), "r"(a[2]), "r"(a[3]), "r"(b0), "r"(b1));
}
__device__ __forceinline__ uint32_t pack_e4m3_4(float a, float b, float c, float d) {
    uint16_t lo, hi;
    asm("cvt.rn.satfinite.e4m3x2.f32 %0, %1, %2;" : "=h"(lo) : "f"(b), "f"(a));
    asm("cvt.rn.satfinite.e4m3x2.f32 %0, %1, %2;" : "=h"(hi) : "f"(d), "f"(c));
    return (uint32_t)lo | ((uint32_t)hi << 16);
}

// ---------------- Kernel: fp32 -> fp8 (scaled); which==0 also zeroes accums --
__global__ void cvt_kernel(const float4* __restrict__ in, int which, size_t n4, float scale) {
    if (which == 0) {
        int gid = blockIdx.x * blockDim.x + threadIdx.x;
        if (gid < BT) {
            g_sumexp[gid] = 0.f; g_ss[gid] = 0.f; g_tt[gid] = 0.f; g_st[gid] = 0.f;
        }
    }
    uint32_t* out;
    switch (which) {
        case 0: out = (uint32_t*)g_s8; break;
        case 1: out = (uint32_t*)g_t8; break;
        case 2: out = (uint32_t*)g_sw8; break;
        default: out = (uint32_t*)g_tw8; break;
    }
    size_t stride = (size_t)gridDim.x * blockDim.x;
    for (size_t i = (size_t)blockIdx.x * blockDim.x + threadIdx.x; i < n4; i += stride) {
        float4 v = in[i];
        out[i] = pack_e4m3_4(v.x * scale, v.y * scale, v.z * scale, v.w * scale);
    }
}

// ---------------- Kernel: exact fp32 target logit -----------------------------
__global__ void tgt_kernel(const float* __restrict__ student,
                           const float* __restrict__ sw,
                           const int* __restrict__ target) {
    int row = blockIdx.x;
    int t = target[row];
    int ct = (t < 0 || t >= VV) ? 0 : t;
    const float4* a = (const float4*)(student + (size_t)row * HS);
    const float4* b = (const float4*)(sw + (size_t)ct * HS);
    float p = 0.f;
    for (int k = threadIdx.x; k < HS / 4; k += blockDim.x) {
        float4 x = a[k]; float4 y = b[k];
        p += x.x * y.x + x.y * y.y + x.z * y.z + x.w * y.w;
    }
    __shared__ float sred[8];
    #pragma unroll
    for (int o = 16; o; o >>= 1) p += __shfl_down_sync(0xffffffffu, p, o);
    if ((threadIdx.x & 31) == 0) sred[threadIdx.x >> 5] = p;
    __syncthreads();
    if (threadIdx.x < 32) {
        p = (threadIdx.x < (blockDim.x >> 5)) ? sred[threadIdx.x] : 0.f;
        #pragma unroll
        for (int o = 16; o; o >>= 1) p += __shfl_down_sync(0xffffffffu, p, o);
        if (threadIdx.x == 0) g_tgt[row] = p;
    }
}

// ---------------- Kernel: two-phase dual FP8 MMA GEMM + row stats ------------
// Grid (16, 125). Block tile 128x256; 16 warps as 4m x 4n, warp tile 32x64.
// 4 warps per SMSP — tests whether legacy mma rate is per-warp-issue bound.
__global__ __launch_bounds__(THREADS, 1) void main_kernel() {
    extern __shared__ char smem[];
    const uint32_t sb = smem_u32(smem);
    const int tid = threadIdx.x;
    const int wid = tid >> 5;
    const int lane = tid & 31;
    const int mw = wid & 3;        // 4 warps in m
    const int nw = wid >> 2;       // 4 warps in n
    const int rb = blockIdx.x * BM;
    const int vb = blockIdx.y * BN;

    const int q = tid & 7;     // 16B chunk within 128B row
    const int r0 = tid >> 3;   // base row 0..63

    float acc[2][8][4];        // 32x64 warp tile
    #pragma unroll
    for (int i = 0; i < 2; i++)
        #pragma unroll
        for (int j = 0; j < 8; j++)
            #pragma unroll
            for (int e = 0; e < 4; e++) acc[i][j][e] = 0.f;

    auto issue = [&](int kt, int s) {
        const bool tea = (kt >= KT_S);
        const int kk = tea ? (kt - KT_S) : kt;
        const uint8_t* Ab = tea ? g_t8 : g_s8;
        const uint8_t* Bb = tea ? g_tw8 : g_sw8;
        const int ldk = tea ? HT : HS;    // bytes per row (1B/elem)
        const uint32_t st = sb + s * STAGE_BYTES;
        #pragma unroll
        for (int c = 0; c < 2; c++) {
            int row = r0 + 64 * c;
            cp_async16(st + SWZ(row * 128 + q * 16),
                       Ab + (size_t)(rb + row) * ldk + kk * BK + q * 16);
        }
        #pragma unroll
        for (int c = 0; c < 4; c++) {
            int row = r0 + 64 * c;
            cp_async16(st + A_BYTES + SWZ(row * 128 + q * 16),
                       Bb + (size_t)(vb + row) * ldk + kk * BK + q * 16);
        }
        cp_commit();
    };

    const int arow = mw * 32 + (lane & 15);   // + mi*16
    const int brow = nw * 64 + (lane & 15);   // + np*16
    const int csel = (lane >> 4) * 16;

    auto step = [&](int kt) __attribute__((always_inline)) {
        const int s = kt % STAGES;
        if (kt < NKT - 1) {
            asm volatile("cp.async.wait_group 1;" ::: "memory");
        } else {
            asm volatile("cp.async.wait_group 0;" ::: "memory");
        }
        __syncthreads();
        if (kt + 2 < NKT) issue(kt + 2, (kt + 2) % STAGES);

        const uint32_t stA = sb + s * STAGE_BYTES;
        const uint32_t stB = stA + A_BYTES;
        #pragma unroll
        for (int kf = 0; kf < 4; kf++) {   // kf covers 32 fp8 bytes
            uint32_t af[2][4], bfv[4][4];
            #pragma unroll
            for (int mi = 0; mi < 2; mi++)
                ldsm_x4(af[mi], stA + SWZ((arow + mi * 16) * 128 + kf * 32 + csel));
            #pragma unroll
            for (int np = 0; np < 4; np++)
                ldsm_x4(bfv[np], stB + SWZ((brow + np * 16) * 128 + kf * 32 + csel));
            #pragma unroll
            for (int mi = 0; mi < 2; mi++)
                #pragma unroll
                for (int np = 0; np < 4; np++) {
                    mma16832(acc[mi][2 * np + 0], af[mi], bfv[np][0], bfv[np][2]);
                    mma16832(acc[mi][2 * np + 1], af[mi], bfv[np][1], bfv[np][3]);
                }
        }
    };

    issue(0, 0);
    issue(1, 1);

    // ---- phase 1: student ----
    for (int kt = 0; kt < KT_S; kt++) step(kt);

    // phase boundary: unscale logits, exp/ss stats, stash s (bf16) in smem.
    {
        const uint32_t lane_col_b = (uint32_t)(nw * 64 + (lane & 3) * 2) * 2;
        #pragma unroll
        for (int mi = 0; mi < 2; mi++) {
            #pragma unroll
            for (int half = 0; half < 2; half++) {
                int row = mw * 32 + mi * 16 + (lane >> 2) + half * 8;
                uint32_t rowoff = sb + SBUF_OFF + (uint32_t)row * SBUF_ROW + lane_col_b;
                float pe = 0.f, pss = 0.f;
                #pragma unroll
                for (int ni = 0; ni < 8; ni++) {
                    float s0 = acc[mi][ni][half * 2 + 0] * ISCALE;
                    float s1 = acc[mi][ni][half * 2 + 1] * ISCALE;
                    pe += __expf(s0) + __expf(s1);
                    pss += s0 * s0 + s1 * s1;
                    __nv_bfloat162 p = __floats2bfloat162_rn(s0, s1);
                    uint32_t pw = *(uint32_t*)&p;
                    asm volatile("st.shared.b32 [%0], %1;" :: "r"(rowoff + ni * 16), "r"(pw) : "memory");
                }
                #pragma unroll
                for (int o = 1; o < 4; o <<= 1) {
                    pe += __shfl_xor_sync(0xffffffffu, pe, o);
                    pss += __shfl_xor_sync(0xffffffffu, pss, o);
                }
                if ((lane & 3) == 0) {
                    atomicAdd(&g_sumexp[rb + row], pe);
                    atomicAdd(&g_ss[rb + row], pss);
                }
            }
        }
        #pragma unroll
        for (int i = 0; i < 2; i++)
            #pragma unroll
            for (int j = 0; j < 8; j++)
                #pragma unroll
                for (int e = 0; e < 4; e++) acc[i][j][e] = 0.f;
    }

    // ---- phase 2: teacher ----
    for (int kt = KT_S; kt < NKT; kt++) step(kt);

    // final epilogue: tt/st stats (s read back from smem, lane-private values).
    {
        const uint32_t lane_col_b = (uint32_t)(nw * 64 + (lane & 3) * 2) * 2;
        #pragma unroll
        for (int mi = 0; mi < 2; mi++) {
            #pragma unroll
            for (int half = 0; half < 2; half++) {
                int row = mw * 32 + mi * 16 + (lane >> 2) + half * 8;
                uint32_t rowoff = sb + SBUF_OFF + (uint32_t)row * SBUF_ROW + lane_col_b;
                float ptt = 0.f, pst = 0.f;
                #pragma unroll
                for (int ni = 0; ni < 8; ni++) {
                    uint32_t pw;
                    asm volatile("ld.shared.b32 %0, [%1];" : "=r"(pw) : "r"(rowoff + ni * 16));
                    __nv_bfloat162 p = *(__nv_bfloat162*)&pw;
                    float s0 = __bfloat162float(p.x);
                    float s1 = __bfloat162float(p.y);
                    float t0 = acc[mi][ni][half * 2 + 0] * ISCALE;
                    float t1 = acc[mi][ni][half * 2 + 1] * ISCALE;
                    ptt += t0 * t0 + t1 * t1;
                    pst += s0 * t0 + s1 * t1;
                }
                #pragma unroll
                for (int o = 1; o < 4; o <<= 1) {
                    ptt += __shfl_xor_sync(0xffffffffu, ptt, o);
                    pst += __shfl_xor_sync(0xffffffffu, pst, o);
                }
                if ((lane & 3) == 0) {
                    atomicAdd(&g_tt[rb + row], ptt);
                    atomicAdd(&g_st[rb + row], pst);
                }
            }
        }
    }
}

// ---------------- Kernel: final scalar loss ----------------------------------
__global__ void final_kernel(const int* __restrict__ target, float* __restrict__ out) {
    __shared__ float sh[8], ssf[8], snv[8];
    float hard = 0.f, soft = 0.f, nv = 0.f;
    for (int i = threadIdx.x; i < BT; i += blockDim.x) {
        int t = target[i];
        bool valid = (t != IGNORE_IDX);
        float lse = logf(g_sumexp[i]);
        if (valid) { hard += lse - g_tgt[i]; nv += 1.f; }
        float cs = g_st[i] * rsqrtf(g_ss[i] + 1e-12f) * rsqrtf(g_tt[i] + 1e-12f);
        soft += 1.f - cs;
    }
    #pragma unroll
    for (int o = 16; o; o >>= 1) {
        hard += __shfl_down_sync(0xffffffffu, hard, o);
        soft += __shfl_down_sync(0xffffffffu, soft, o);
        nv += __shfl_down_sync(0xffffffffu, nv, o);
    }
    int w = threadIdx.x >> 5, l = threadIdx.x & 31;
    if (l == 0) { sh[w] = hard; ssf[w] = soft; snv[w] = nv; }
    __syncthreads();
    if (threadIdx.x < 32) {
        int nw = blockDim.x >> 5;
        hard = (threadIdx.x < nw) ? sh[threadIdx.x] : 0.f;
        soft = (threadIdx.x < nw) ? ssf[threadIdx.x] : 0.f;
        nv = (threadIdx.x < nw) ? snv[threadIdx.x] : 0.f;
        #pragma unroll
        for (int o = 16; o; o >>= 1) {
            hard += __shfl_down_sync(0xffffffffu, hard, o);
            soft += __shfl_down_sync(0xffffffffu, soft, o);
            nv += __shfl_down_sync(0xffffffffu, nv, o);
        }
        if (threadIdx.x == 0)
            out[0] = 0.5f * hard / nv + 0.5f * soft / nv;
    }
}

// ---------------- launch ------------------------------------------------------
extern "C" void kernel_launch(void* const* d_in, const int* in_sizes, int n_in,
                              void* d_out, int out_size) {
    const float* student = (const float*)d_in[0];
    const float* teacher = (const float*)d_in[1];
    const int* target = (const int*)d_in[2];
    const float* sw = (const float*)d_in[3];
    const float* tw = (const float*)d_in[4];
    float* out = (float*)d_out;

    cudaFuncSetAttribute(main_kernel, cudaFuncAttributeMaxDynamicSharedMemorySize, SMEM_BYTES);

    cvt_kernel<<<2048, 256>>>((const float4*)student, 0, (size_t)BT * HS / 4, 1.0f);
    cvt_kernel<<<2048, 256>>>((const float4*)teacher, 1, (size_t)BT * HT / 4, 1.0f);
    cvt_kernel<<<4096, 256>>>((const float4*)sw, 2, (size_t)VV * HS / 4, WSCALE);
    cvt_kernel<<<4096, 256>>>((const float4*)tw, 3, (size_t)VV * HT / 4, WSCALE);
    tgt_kernel<<<BT, 128>>>(student, sw, target);
    dim3 grid(BT / BM, VV / BN);  // (16, 125)
    main_kernel<<<grid, THREADS, SMEM_BYTES>>>();
    final_kernel<<<1, 256>>>(target, out);
}